// round 14
// baseline (speedup 1.0000x reference)
#include <cuda_runtime.h>
#include <math.h>

// ---------------------------------------------------------------------------
// PrettyPCF, R14: in-block spatial binning, warp-per-i, JSPLIT=1.
//  * Each block counting-sorts ALL 1536 B points into a 5x5 cell grid in
//    shared memory (cell 0.2 > cutoff 0.17): histogram -> warp scan ->
//    scatter. Cost ~ same as the flat B staging it replaces.
//  * Each warp owns ONE i-point; candidates = 3 contiguous sorted ranges
//    (3x3 neighbor cells) ~ 415 pts avg instead of 1536 (3.7x less phase A).
//  * Weight prologue paid ONCE per i (JSPLIT=1) + warp-uniform interior
//    skip (48% of points: all edges > 5*RMAX -> w=1).
//  * Proven pieces kept: ballot+popc compacted warp queue, branchless
//    4-way unrolled drain, rcp/ex2 approx, polynomial acos/atan2,
//    lane==bin register weights, done-counter finalize.
//  * 192 blocks x 256 thr, ~26KB smem -> all blocks co-resident, one wave.
// ---------------------------------------------------------------------------

#define NPTS   1536
#define NBINS  50
#define WPB    8                   // warps (== i-points) per block
#define NTHR   (WPB * 32)          // 256
#define NBLK   (NPTS / WPB)        // 192
#define G      5                   // grid cells per side (cell = 0.2)
#define NCELL  (G * G)             // 25
#define PPT    (NPTS / NTHR)       // 6 points per thread in binning
#define QW     320                 // per-warp queue capacity (max ~200 seen)
#define ZC     1.2f

#define RMAX_D (2.0 * sqrt(1.0 / (2.0 * sqrt(3.0) * 1536.0)))

__device__ float g_acc[NBINS];   // zero-init at load; reset by last block
__device__ int   g_done;

__device__ __forceinline__ float ex2_fast(float x) {
    float y;
    asm("ex2.approx.ftz.f32 %0, %1;" : "=f"(y) : "f"(x));
    return y;
}
__device__ __forceinline__ float rcp_fast(float x) {
    float y;
    asm("rcp.approx.ftz.f32 %0, %1;" : "=f"(y) : "f"(x));
    return y;
}

// acos(x), x in [0,1]; abs err < 6.7e-5 (A&S 4.4.45). acos(1) = 0 exactly.
__device__ __forceinline__ float acos_poly(float x) {
    float p = fmaf(x, fmaf(x, fmaf(x, -0.0187293f, 0.0742610f),
                               -0.2121144f), 1.5707288f);
    return sqrtf(1.0f - x) * p;
}

// atan(r), r in [0,1]; minimax odd poly, abs err ~1e-6.
__device__ __forceinline__ float atan_poly(float r) {
    float r2 = r * r;
    float p = fmaf(r2, fmaf(r2, fmaf(r2, fmaf(r2, fmaf(r2,
              -0.0117212f, 0.05265332f), -0.11643287f),
               0.19354346f), -0.33262347f), 0.99997726f);
    return r * p;
}

// atan2(y, x) for x,y >= 0 (first quadrant), branchless, rcp-based.
__device__ __forceinline__ float atan2_q1(float y, float x) {
    float mn = fminf(x, y);
    float mx = fmaxf(x, y);
    float r  = mn * rcp_fast(fmaxf(mx, 1e-20f));
    float a  = atan_poly(r);
    return (y > x) ? (1.5707963268f - a) : a;
}

__global__ __launch_bounds__(NTHR)
void pcf_kernel(const float* __restrict__ A, const float* __restrict__ B,
                const int* __restrict__ scp, float* __restrict__ out)
{
    __shared__ float2 sbp[NPTS];             // binned B points (u-units)
    __shared__ unsigned short sbj[NPTS];     // original j index
    __shared__ int   scellstart[NCELL + 1];
    __shared__ int   scnt[NCELL];
    __shared__ float swq[WPB * QW];          // per-warp survivor u's
    __shared__ float sacc[NBINS];
    __shared__ int   is_last;

    const int tid  = threadIdx.x;
    const int lane = tid & 31;
    const int wid  = tid >> 5;
    const int i    = blockIdx.x * WPB + wid;   // this warp's i-point
    float* wq = &swq[wid * QW];

    const float invR = (float)(1.0 / RMAX_D);

    // ---- Binning pass 1: load 6 pts/thread, histogram cells ----
    if (tid < NCELL) scnt[tid] = 0;
    if (tid < NBINS) sacc[tid] = 0.0f;
    __syncthreads();

    float bxr[PPT], byr[PPT];
    int   cidr[PPT];
#pragma unroll
    for (int k = 0; k < PPT; k++) {
        int j = tid + k * NTHR;
        float x = B[3 * j];
        float y = B[3 * j + 1];
        int cx = min(G - 1, (int)(x * (float)G));
        int cy = min(G - 1, (int)(y * (float)G));
        int c  = cy * G + cx;
        bxr[k] = x * invR;
        byr[k] = y * invR;
        cidr[k] = c;
        atomicAdd(&scnt[c], 1);
    }
    __syncthreads();

    // ---- Exclusive scan of 25 cell counts (warp 0) ----
    if (wid == 0) {
        int c = (lane < NCELL) ? scnt[lane] : 0;
#pragma unroll
        for (int off = 1; off < 32; off <<= 1) {
            int n = __shfl_up_sync(0xFFFFFFFFu, c, off);
            if (lane >= off) c += n;
        }
        if (lane < NCELL) scellstart[lane + 1] = c;
        if (lane == 0)    scellstart[0] = 0;
        if (lane < NCELL) scnt[lane] = 0;    // reuse as scatter cursor
    }
    __syncthreads();

    // ---- Binning pass 2: scatter ----
#pragma unroll
    for (int k = 0; k < PPT; k++) {
        int c = cidr[k];
        int slot = scellstart[c] + atomicAdd(&scnt[c], 1);
        sbp[slot] = make_float2(bxr[k], byr[k]);
        sbj[slot] = (unsigned short)(tid + k * NTHR);
    }

    // ---- This warp's i coords + weights (overlap with scatter latency) ----
    const float ax = A[3 * i];
    const float ay = A[3 * i + 1];
    const float axs = ax * invR;
    const float ays = ay * invR;

    const float TWO_PI = 6.2831853071795864769f;
    const float ex0 = ax,  ex1 = 1.0f - ax;
    const float ex2v = ay, ex3 = 1.0f - ay;
    const float mEdge = fminf(fminf(ex0, ex1), fminf(ex2v, ex3));
    const float rsMax = (float)(5.0 * RMAX_D);

    float w1 = 1.0f, w2 = 1.0f;
    if (mEdge < rsMax) {            // warp-uniform: i near a border
        // atan2 edge terms: lanes 0-7 compute, shfl-broadcast
        float aval = 0.0f;
        if (lane < 8) {
            int e     = lane >> 1;
            int which = lane & 1;
            float exk = (e == 0) ? ax : (e == 1) ? (1.0f - ax)
                      : (e == 2) ? ay : (1.0f - ay);
            float eyk = (e < 2) ? ay : ax;
            float yy  = which ? (1.0f - eyk) : eyk;
            aval = atan2_q1(yy, exk);
        }
        const float a10 = __shfl_sync(0xFFFFFFFFu, aval, 0);
        const float a20 = __shfl_sync(0xFFFFFFFFu, aval, 1);
        const float a11 = __shfl_sync(0xFFFFFFFFu, aval, 2);
        const float a21 = __shfl_sync(0xFFFFFFFFu, aval, 3);
        const float a12 = __shfl_sync(0xFFFFFFFFu, aval, 4);
        const float a22 = __shfl_sync(0xFFFFFFFFu, aval, 5);
        const float a13 = __shfl_sync(0xFFFFFFFFu, aval, 6);
        const float a23 = __shfl_sync(0xFFFFFFFFu, aval, 7);

        const float rs1 = (float)((lane +  1) * (5.0 / 50.0) * RMAX_D);
        const float rs2 = (float)((lane + 33) * (5.0 / 50.0) * RMAX_D);
        {
            float ir = rcp_fast(rs1);
            float al0 = acos_poly(fminf(ex0  * ir, 1.0f));
            float al1 = acos_poly(fminf(ex1  * ir, 1.0f));
            float al2 = acos_poly(fminf(ex2v * ir, 1.0f));
            float al3 = acos_poly(fminf(ex3  * ir, 1.0f));
            float full = TWO_PI
                - (fminf(al0, a10) + fminf(al0, a20))
                - (fminf(al1, a11) + fminf(al1, a21))
                - (fminf(al2, a12) + fminf(al2, a22))
                - (fminf(al3, a13) + fminf(al3, a23));
            float per = fminf(fmaxf(full * (1.0f / TWO_PI), 0.0f), 1.0f);
            w1 = fminf(rcp_fast(fmaxf(per, 1e-9f)), 4.0f);
        }
        {
            float ir = rcp_fast(rs2);
            float al0 = acos_poly(fminf(ex0  * ir, 1.0f));
            float al1 = acos_poly(fminf(ex1  * ir, 1.0f));
            float al2 = acos_poly(fminf(ex2v * ir, 1.0f));
            float al3 = acos_poly(fminf(ex3  * ir, 1.0f));
            float full = TWO_PI
                - (fminf(al0, a10) + fminf(al0, a20))
                - (fminf(al1, a11) + fminf(al1, a21))
                - (fminf(al2, a12) + fminf(al2, a22))
                - (fminf(al3, a13) + fminf(al3, a23));
            float per = fminf(fmaxf(full * (1.0f / TWO_PI), 0.0f), 1.0f);
            w2 = fminf(rcp_fast(fmaxf(per, 1e-9f)), 4.0f);
        }
    }
    if (lane >= NBINS - 32) w2 = 0.0f;   // dead bins contribute 0

    // ---- exp2 coefficients: exp(-16 (zb-u)^2) = ex2(c0 + c1 u + c2 u^2) ----
    const float L2E = 1.4426950408889634f;
    const float c2  = -16.0f * L2E;
    const float zb1 = 0.1f * (float)(lane + 1);
    const float zb2 = zb1 + 3.2f;
    const float c1a = 32.0f * zb1 * L2E;
    const float c0a = -16.0f * zb1 * zb1 * L2E;
    const float c1b = 32.0f * zb2 * L2E;
    const float c0b = -16.0f * zb2 * zb2 * L2E;

    const int   same = *scp;
    const float cut2 = (5.0f + ZC) * (5.0f + ZC);   // u-units

    __syncthreads();   // sbp/sbj/scellstart ready

    // ---- Phase A: candidates from 3 contiguous neighbor-cell ranges ----
    int cix = min(G - 1, (int)(ax * (float)G));
    int ciy = min(G - 1, (int)(ay * (float)G));
    int cxlo = max(cix - 1, 0), cxhi = min(cix + 1, G - 1);
    int cylo = max(ciy - 1, 0), cyhi = min(ciy + 1, G - 1);

    int cnt = 0;
    const unsigned lt_mask = (1u << lane) - 1u;
    for (int r = cylo; r <= cyhi; r++) {
        int lo = scellstart[r * G + cxlo];
        int hi = scellstart[r * G + cxhi + 1];
        for (int base = lo; base < hi; base += 32) {
            int jl = base + lane;
            int jc = min(jl, NPTS - 1);
            float2 p = sbp[jc];
            float dx = axs - p.x;
            float dy = ays - p.y;
            float d2 = fmaf(dx, dx, dy * dy);
            bool pred = (jl < hi) && (d2 < cut2)
                        && !(same && i == (int)sbj[jc]);
            unsigned mask = __ballot_sync(0xFFFFFFFFu, pred);
            if (pred) {
                int slot = cnt + __popc(mask & lt_mask);
                if (slot < QW) wq[slot] = sqrtf(d2);   // u = d/RMAX
            }
            cnt += __popc(mask);
        }
    }
    if (cnt > QW) cnt = QW;
    __syncwarp();

    // ---- Phase B: branchless 4-way unrolled drain ----
    float acc1 = 0.0f, acc2 = 0.0f;
    int e = 0;
    for (; e + 3 < cnt; e += 4) {
        float uA = wq[e],     uB = wq[e + 1];
        float uC = wq[e + 2], uD = wq[e + 3];
        float uA2 = uA * uA, uB2 = uB * uB;
        float uC2 = uC * uC, uD2 = uD * uD;
        float gA1 = ex2_fast(fmaf(c2, uA2, fmaf(c1a, uA, c0a)));
        float gB1 = ex2_fast(fmaf(c2, uB2, fmaf(c1a, uB, c0a)));
        float gC1 = ex2_fast(fmaf(c2, uC2, fmaf(c1a, uC, c0a)));
        float gD1 = ex2_fast(fmaf(c2, uD2, fmaf(c1a, uD, c0a)));
        float gA2 = ex2_fast(fmaf(c2, uA2, fmaf(c1b, uA, c0b)));
        float gB2 = ex2_fast(fmaf(c2, uB2, fmaf(c1b, uB, c0b)));
        float gC2 = ex2_fast(fmaf(c2, uC2, fmaf(c1b, uC, c0b)));
        float gD2 = ex2_fast(fmaf(c2, uD2, fmaf(c1b, uD, c0b)));
        acc1 = fmaf(gA1, w1, acc1);
        acc1 = fmaf(gB1, w1, acc1);
        acc1 = fmaf(gC1, w1, acc1);
        acc1 = fmaf(gD1, w1, acc1);
        acc2 = fmaf(gA2, w2, acc2);
        acc2 = fmaf(gB2, w2, acc2);
        acc2 = fmaf(gC2, w2, acc2);
        acc2 = fmaf(gD2, w2, acc2);
    }
    for (; e < cnt; e++) {
        float u  = wq[e];
        float u2 = u * u;
        acc1 = fmaf(ex2_fast(fmaf(c2, u2, fmaf(c1a, u, c0a))), w1, acc1);
        acc2 = fmaf(ex2_fast(fmaf(c2, u2, fmaf(c1b, u, c0b))), w2, acc2);
    }

    // ---- Block reduction -> global ----
    atomicAdd(&sacc[lane], acc1);
    if (lane < NBINS - 32) atomicAdd(&sacc[lane + 32], acc2);
    __syncthreads();
    if (tid < NBINS) atomicAdd(&g_acc[tid], sacc[tid]);

    // ---- Last block finalizes ----
    __threadfence();
    if (tid == 0) {
        int v = atomicAdd(&g_done, 1);
        is_last = (v == NBLK - 1);
    }
    __syncthreads();
    if (is_last) {
        if (tid < NBINS) {
            int b = tid;
            double rs_d  = (b + 1) * (5.0 / 50.0) * RMAX_D;
            double inner = fmax(0.0, rs_d - 0.5 * RMAX_D);
            double outer = rs_d + 0.5 * RMAX_D;
            float  area  = (float)(M_PI * (outer * outer - inner * inner));
            const float GF = (float)(1.0 / (sqrt(M_PI) * 0.25));

            float s   = g_acc[b] * GF;
            float pcf = s / 1536.0f / (area * 1536.0f);

            out[2 * b]     = (float)rs_d / (float)RMAX_D;
            out[2 * b + 1] = pcf;

            g_acc[b] = 0.0f;          // reset for next graph replay
        }
        if (tid == 0) g_done = 0;
    }
}

// ---------------------------------------------------------------------------
extern "C" void kernel_launch(void* const* d_in, const int* in_sizes, int n_in,
                              void* d_out, int out_size)
{
    const float* A  = (const float*)d_in[0];   // disks_a [1536,3]
    const float* B  = (const float*)d_in[1];   // disks_b [1536,3]
    const int*   sc = (const int*)d_in[2];     // same_category scalar
    float* out = (float*)d_out;

    pcf_kernel<<<NBLK, NTHR>>>(A, B, sc, out);
}

// round 15
// speedup vs baseline: 1.0829x; 1.0829x over previous
#include <cuda_runtime.h>
#include <math.h>

// ---------------------------------------------------------------------------
// PrettyPCF, R15 = R14 binning + 3x warp parallelism (warp per (i, cellrow)).
//  * Each block counting-sorts all 1536 B points into a 5x5 grid in smem.
//  * Warp task = (i-point, one of its <=3 neighbor cell rows): 4608 tasks,
//    384 blocks x 12 warps -> ~31 warps/SM (R14 had 10).
//  * Weight prologue duplicated x3 per i (cheap: interior skip + polys).
//  * Proven: ballot+popc compacted queue, branchless 4-way drain,
//    rcp/ex2 approx, lane==bin register weights, done-counter finalize.
// ---------------------------------------------------------------------------

#define NPTS   1536
#define NBINS  50
#define WPB_I  4                   // i-points per block
#define NWARP  (WPB_I * 3)         // 12 warps (3 row-warps per i)
#define NTHR   (NWARP * 32)        // 384
#define NBLK   (NPTS / WPB_I)      // 384
#define G      5                   // grid cells per side (cell = 0.2)
#define NCELL  (G * G)             // 25
#define PPT    (NPTS / NTHR)       // 4 points per thread in binning
#define QW     320                 // per-warp queue capacity (1 row <=~250)
#define ZC     1.2f

#define RMAX_D (2.0 * sqrt(1.0 / (2.0 * sqrt(3.0) * 1536.0)))

__device__ float g_acc[NBINS];   // zero-init at load; reset by last block
__device__ int   g_done;

__device__ __forceinline__ float ex2_fast(float x) {
    float y;
    asm("ex2.approx.ftz.f32 %0, %1;" : "=f"(y) : "f"(x));
    return y;
}
__device__ __forceinline__ float rcp_fast(float x) {
    float y;
    asm("rcp.approx.ftz.f32 %0, %1;" : "=f"(y) : "f"(x));
    return y;
}

// acos(x), x in [0,1]; abs err < 6.7e-5 (A&S 4.4.45). acos(1) = 0 exactly.
__device__ __forceinline__ float acos_poly(float x) {
    float p = fmaf(x, fmaf(x, fmaf(x, -0.0187293f, 0.0742610f),
                               -0.2121144f), 1.5707288f);
    return sqrtf(1.0f - x) * p;
}

// atan(r), r in [0,1]; minimax odd poly, abs err ~1e-6.
__device__ __forceinline__ float atan_poly(float r) {
    float r2 = r * r;
    float p = fmaf(r2, fmaf(r2, fmaf(r2, fmaf(r2, fmaf(r2,
              -0.0117212f, 0.05265332f), -0.11643287f),
               0.19354346f), -0.33262347f), 0.99997726f);
    return r * p;
}

// atan2(y, x) for x,y >= 0 (first quadrant), branchless, rcp-based.
__device__ __forceinline__ float atan2_q1(float y, float x) {
    float mn = fminf(x, y);
    float mx = fmaxf(x, y);
    float r  = mn * rcp_fast(fmaxf(mx, 1e-20f));
    float a  = atan_poly(r);
    return (y > x) ? (1.5707963268f - a) : a;
}

__global__ __launch_bounds__(NTHR)
void pcf_kernel(const float* __restrict__ A, const float* __restrict__ B,
                const int* __restrict__ scp, float* __restrict__ out)
{
    __shared__ float2 sbp[NPTS];             // binned B points (u-units)
    __shared__ unsigned short sbj[NPTS];     // original j index
    __shared__ int   scellstart[NCELL + 1];
    __shared__ int   scnt[NCELL];
    __shared__ float swq[NWARP * QW];        // per-warp survivor u's
    __shared__ float sacc[NBINS];
    __shared__ int   is_last;

    const int tid  = threadIdx.x;
    const int lane = tid & 31;
    const int wid  = tid >> 5;
    const int iloc = wid / 3;                // which of this block's 4 i's
    const int sub  = wid - iloc * 3;         // which neighbor cell-row (0..2)
    const int i    = blockIdx.x * WPB_I + iloc;
    float* wq = &swq[wid * QW];

    const float invR = (float)(1.0 / RMAX_D);

    // ---- Binning pass 1: load 4 pts/thread, histogram cells ----
    if (tid < NCELL) scnt[tid] = 0;
    if (tid < NBINS) sacc[tid] = 0.0f;
    __syncthreads();

    float bxr[PPT], byr[PPT];
    int   cidr[PPT];
#pragma unroll
    for (int k = 0; k < PPT; k++) {
        int j = tid + k * NTHR;
        float x = B[3 * j];
        float y = B[3 * j + 1];
        int cx = min(G - 1, (int)(x * (float)G));
        int cy = min(G - 1, (int)(y * (float)G));
        int c  = cy * G + cx;
        bxr[k] = x * invR;
        byr[k] = y * invR;
        cidr[k] = c;
        atomicAdd(&scnt[c], 1);
    }
    __syncthreads();

    // ---- Exclusive scan of 25 cell counts (warp 0) ----
    if (wid == 0) {
        int c = (lane < NCELL) ? scnt[lane] : 0;
#pragma unroll
        for (int off = 1; off < 32; off <<= 1) {
            int n = __shfl_up_sync(0xFFFFFFFFu, c, off);
            if (lane >= off) c += n;
        }
        if (lane < NCELL) scellstart[lane + 1] = c;
        if (lane == 0)    scellstart[0] = 0;
        if (lane < NCELL) scnt[lane] = 0;    // reuse as scatter cursor
    }
    __syncthreads();

    // ---- Binning pass 2: scatter ----
#pragma unroll
    for (int k = 0; k < PPT; k++) {
        int c = cidr[k];
        int slot = scellstart[c] + atomicAdd(&scnt[c], 1);
        sbp[slot] = make_float2(bxr[k], byr[k]);
        sbj[slot] = (unsigned short)(tid + k * NTHR);
    }

    // ---- This warp's i coords + weights (overlap scatter latency) ----
    const float ax = A[3 * i];
    const float ay = A[3 * i + 1];
    const float axs = ax * invR;
    const float ays = ay * invR;

    const float TWO_PI = 6.2831853071795864769f;
    const float ex0 = ax,  ex1 = 1.0f - ax;
    const float ex2v = ay, ex3 = 1.0f - ay;
    const float mEdge = fminf(fminf(ex0, ex1), fminf(ex2v, ex3));
    const float rsMax = (float)(5.0 * RMAX_D);

    float w1 = 1.0f, w2 = 1.0f;
    if (mEdge < rsMax) {            // warp-uniform: i near a border
        float aval = 0.0f;
        if (lane < 8) {
            int e     = lane >> 1;
            int which = lane & 1;
            float exk = (e == 0) ? ax : (e == 1) ? (1.0f - ax)
                      : (e == 2) ? ay : (1.0f - ay);
            float eyk = (e < 2) ? ay : ax;
            float yy  = which ? (1.0f - eyk) : eyk;
            aval = atan2_q1(yy, exk);
        }
        const float a10 = __shfl_sync(0xFFFFFFFFu, aval, 0);
        const float a20 = __shfl_sync(0xFFFFFFFFu, aval, 1);
        const float a11 = __shfl_sync(0xFFFFFFFFu, aval, 2);
        const float a21 = __shfl_sync(0xFFFFFFFFu, aval, 3);
        const float a12 = __shfl_sync(0xFFFFFFFFu, aval, 4);
        const float a22 = __shfl_sync(0xFFFFFFFFu, aval, 5);
        const float a13 = __shfl_sync(0xFFFFFFFFu, aval, 6);
        const float a23 = __shfl_sync(0xFFFFFFFFu, aval, 7);

        const float rs1 = (float)((lane +  1) * (5.0 / 50.0) * RMAX_D);
        const float rs2 = (float)((lane + 33) * (5.0 / 50.0) * RMAX_D);
        {
            float ir = rcp_fast(rs1);
            float al0 = acos_poly(fminf(ex0  * ir, 1.0f));
            float al1 = acos_poly(fminf(ex1  * ir, 1.0f));
            float al2 = acos_poly(fminf(ex2v * ir, 1.0f));
            float al3 = acos_poly(fminf(ex3  * ir, 1.0f));
            float full = TWO_PI
                - (fminf(al0, a10) + fminf(al0, a20))
                - (fminf(al1, a11) + fminf(al1, a21))
                - (fminf(al2, a12) + fminf(al2, a22))
                - (fminf(al3, a13) + fminf(al3, a23));
            float per = fminf(fmaxf(full * (1.0f / TWO_PI), 0.0f), 1.0f);
            w1 = fminf(rcp_fast(fmaxf(per, 1e-9f)), 4.0f);
        }
        {
            float ir = rcp_fast(rs2);
            float al0 = acos_poly(fminf(ex0  * ir, 1.0f));
            float al1 = acos_poly(fminf(ex1  * ir, 1.0f));
            float al2 = acos_poly(fminf(ex2v * ir, 1.0f));
            float al3 = acos_poly(fminf(ex3  * ir, 1.0f));
            float full = TWO_PI
                - (fminf(al0, a10) + fminf(al0, a20))
                - (fminf(al1, a11) + fminf(al1, a21))
                - (fminf(al2, a12) + fminf(al2, a22))
                - (fminf(al3, a13) + fminf(al3, a23));
            float per = fminf(fmaxf(full * (1.0f / TWO_PI), 0.0f), 1.0f);
            w2 = fminf(rcp_fast(fmaxf(per, 1e-9f)), 4.0f);
        }
    }
    if (lane >= NBINS - 32) w2 = 0.0f;   // dead bins contribute 0

    // ---- exp2 coefficients ----
    const float L2E = 1.4426950408889634f;
    const float c2  = -16.0f * L2E;
    const float zb1 = 0.1f * (float)(lane + 1);
    const float zb2 = zb1 + 3.2f;
    const float c1a = 32.0f * zb1 * L2E;
    const float c0a = -16.0f * zb1 * zb1 * L2E;
    const float c1b = 32.0f * zb2 * L2E;
    const float c0b = -16.0f * zb2 * zb2 * L2E;

    const int   same = *scp;
    const float cut2 = (5.0f + ZC) * (5.0f + ZC);   // u-units

    __syncthreads();   // sbp/sbj/scellstart ready

    // ---- Phase A: this warp scans ONE neighbor cell-row of its i ----
    int cix = min(G - 1, (int)(ax * (float)G));
    int ciy = min(G - 1, (int)(ay * (float)G));
    int cxlo = max(cix - 1, 0), cxhi = min(cix + 1, G - 1);
    int cylo = max(ciy - 1, 0), cyhi = min(ciy + 1, G - 1);
    int r    = cylo + sub;                   // this warp's row

    int cnt = 0;
    if (r <= cyhi) {
        int lo = scellstart[r * G + cxlo];
        int hi = scellstart[r * G + cxhi + 1];
        const unsigned lt_mask = (1u << lane) - 1u;
        for (int base = lo; base < hi; base += 32) {
            int jl = base + lane;
            int jc = min(jl, NPTS - 1);
            float2 p = sbp[jc];
            float dx = axs - p.x;
            float dy = ays - p.y;
            float d2 = fmaf(dx, dx, dy * dy);
            bool pred = (jl < hi) && (d2 < cut2)
                        && !(same && i == (int)sbj[jc]);
            unsigned mask = __ballot_sync(0xFFFFFFFFu, pred);
            if (pred) {
                int slot = cnt + __popc(mask & lt_mask);
                if (slot < QW) wq[slot] = sqrtf(d2);   // u = d/RMAX
            }
            cnt += __popc(mask);
        }
        if (cnt > QW) cnt = QW;
    }
    __syncwarp();

    // ---- Phase B: branchless 4-way unrolled drain ----
    float acc1 = 0.0f, acc2 = 0.0f;
    int e = 0;
    for (; e + 3 < cnt; e += 4) {
        float uA = wq[e],     uB = wq[e + 1];
        float uC = wq[e + 2], uD = wq[e + 3];
        float uA2 = uA * uA, uB2 = uB * uB;
        float uC2 = uC * uC, uD2 = uD * uD;
        float gA1 = ex2_fast(fmaf(c2, uA2, fmaf(c1a, uA, c0a)));
        float gB1 = ex2_fast(fmaf(c2, uB2, fmaf(c1a, uB, c0a)));
        float gC1 = ex2_fast(fmaf(c2, uC2, fmaf(c1a, uC, c0a)));
        float gD1 = ex2_fast(fmaf(c2, uD2, fmaf(c1a, uD, c0a)));
        float gA2 = ex2_fast(fmaf(c2, uA2, fmaf(c1b, uA, c0b)));
        float gB2 = ex2_fast(fmaf(c2, uB2, fmaf(c1b, uB, c0b)));
        float gC2 = ex2_fast(fmaf(c2, uC2, fmaf(c1b, uC, c0b)));
        float gD2 = ex2_fast(fmaf(c2, uD2, fmaf(c1b, uD, c0b)));
        acc1 = fmaf(gA1, w1, acc1);
        acc1 = fmaf(gB1, w1, acc1);
        acc1 = fmaf(gC1, w1, acc1);
        acc1 = fmaf(gD1, w1, acc1);
        acc2 = fmaf(gA2, w2, acc2);
        acc2 = fmaf(gB2, w2, acc2);
        acc2 = fmaf(gC2, w2, acc2);
        acc2 = fmaf(gD2, w2, acc2);
    }
    for (; e < cnt; e++) {
        float u  = wq[e];
        float u2 = u * u;
        acc1 = fmaf(ex2_fast(fmaf(c2, u2, fmaf(c1a, u, c0a))), w1, acc1);
        acc2 = fmaf(ex2_fast(fmaf(c2, u2, fmaf(c1b, u, c0b))), w2, acc2);
    }

    // ---- Block reduction -> global ----
    atomicAdd(&sacc[lane], acc1);
    if (lane < NBINS - 32) atomicAdd(&sacc[lane + 32], acc2);
    __syncthreads();
    if (tid < NBINS) atomicAdd(&g_acc[tid], sacc[tid]);

    // ---- Last block finalizes ----
    __threadfence();
    if (tid == 0) {
        int v = atomicAdd(&g_done, 1);
        is_last = (v == NBLK - 1);
    }
    __syncthreads();
    if (is_last) {
        if (tid < NBINS) {
            int b = tid;
            double rs_d  = (b + 1) * (5.0 / 50.0) * RMAX_D;
            double inner = fmax(0.0, rs_d - 0.5 * RMAX_D);
            double outer = rs_d + 0.5 * RMAX_D;
            float  area  = (float)(M_PI * (outer * outer - inner * inner));
            const float GF = (float)(1.0 / (sqrt(M_PI) * 0.25));

            float s   = g_acc[b] * GF;
            float pcf = s / 1536.0f / (area * 1536.0f);

            out[2 * b]     = (float)rs_d / (float)RMAX_D;
            out[2 * b + 1] = pcf;

            g_acc[b] = 0.0f;          // reset for next graph replay
        }
        if (tid == 0) g_done = 0;
    }
}

// ---------------------------------------------------------------------------
extern "C" void kernel_launch(void* const* d_in, const int* in_sizes, int n_in,
                              void* d_out, int out_size)
{
    const float* A  = (const float*)d_in[0];   // disks_a [1536,3]
    const float* B  = (const float*)d_in[1];   // disks_b [1536,3]
    const int*   sc = (const int*)d_in[2];     // same_category scalar
    float* out = (float*)d_out;

    pcf_kernel<<<NBLK, NTHR>>>(A, B, sc, out);
}

// round 16
// speedup vs baseline: 1.1209x; 1.0351x over previous
#include <cuda_runtime.h>
#include <math.h>

// ---------------------------------------------------------------------------
// PrettyPCF, R16 = R15 binning + BLOCK-BALANCED drain.
//  * R15 facts: instr count halved vs R9 but time flat -> stall/imbalance
//    bound, not instruction bound. Fix: all 12 warps drain ALL 12 queues
//    (strided), so drain work is balanced to +-1 entry per queue.
//  * Queue q holds survivors of i-point q/3 -> its weight pair is UNIFORM:
//    one float2 LDS per queue from a 4x32 smem table (written once per i
//    by the sub==0 warp). Per-entry drain drops to ~11 warp-instr.
//  * Weights computed once per i (not 3x). Phase A stores raw u floats.
//  * Kept: in-block 5x5 counting sort, ballot+popc compaction, rcp/ex2
//    approx, polynomial acos/atan2, done-counter finalize.
// ---------------------------------------------------------------------------

#define NPTS   1536
#define NBINS  50
#define WPB_I  4                   // i-points per block
#define NWARP  (WPB_I * 3)         // 12 warps (3 row-warps per i)
#define NTHR   (NWARP * 32)        // 384
#define NBLK   (NPTS / WPB_I)      // 384
#define G      5                   // grid cells per side (cell = 0.2)
#define NCELL  (G * G)             // 25
#define PPT    (NPTS / NTHR)       // 4 points per thread in binning
#define QW     320                 // per-warp queue capacity
#define ZC     1.2f

#define RMAX_D (2.0 * sqrt(1.0 / (2.0 * sqrt(3.0) * 1536.0)))

__device__ float g_acc[NBINS];   // zero-init at load; reset by last block
__device__ int   g_done;

__device__ __forceinline__ float ex2_fast(float x) {
    float y;
    asm("ex2.approx.ftz.f32 %0, %1;" : "=f"(y) : "f"(x));
    return y;
}
__device__ __forceinline__ float rcp_fast(float x) {
    float y;
    asm("rcp.approx.ftz.f32 %0, %1;" : "=f"(y) : "f"(x));
    return y;
}

// acos(x), x in [0,1]; abs err < 6.7e-5 (A&S 4.4.45). acos(1) = 0 exactly.
__device__ __forceinline__ float acos_poly(float x) {
    float p = fmaf(x, fmaf(x, fmaf(x, -0.0187293f, 0.0742610f),
                               -0.2121144f), 1.5707288f);
    return sqrtf(1.0f - x) * p;
}

// atan(r), r in [0,1]; minimax odd poly, abs err ~1e-6.
__device__ __forceinline__ float atan_poly(float r) {
    float r2 = r * r;
    float p = fmaf(r2, fmaf(r2, fmaf(r2, fmaf(r2, fmaf(r2,
              -0.0117212f, 0.05265332f), -0.11643287f),
               0.19354346f), -0.33262347f), 0.99997726f);
    return r * p;
}

// atan2(y, x) for x,y >= 0 (first quadrant), branchless, rcp-based.
__device__ __forceinline__ float atan2_q1(float y, float x) {
    float mn = fminf(x, y);
    float mx = fmaxf(x, y);
    float r  = mn * rcp_fast(fmaxf(mx, 1e-20f));
    float a  = atan_poly(r);
    return (y > x) ? (1.5707963268f - a) : a;
}

__global__ __launch_bounds__(NTHR)
void pcf_kernel(const float* __restrict__ A, const float* __restrict__ B,
                const int* __restrict__ scp, float* __restrict__ out)
{
    __shared__ float2 sbp[NPTS];             // binned B points (u-units)
    __shared__ unsigned short sbj[NPTS];     // original j index
    __shared__ int   scellstart[NCELL + 1];
    __shared__ int   scnt[NCELL];
    __shared__ float swq[NWARP * QW];        // per-warp survivor u's
    __shared__ int   scnt_w[NWARP];          // per-warp survivor counts
    __shared__ float2 sw12[WPB_I * 32];      // (w1,w2) per (iloc, lane)
    __shared__ float sacc[NBINS];
    __shared__ int   is_last;

    const int tid  = threadIdx.x;
    const int lane = tid & 31;
    const int wid  = tid >> 5;
    const int iloc = wid / 3;                // which of this block's 4 i's
    const int sub  = wid - iloc * 3;         // which neighbor cell-row (0..2)
    const int i    = blockIdx.x * WPB_I + iloc;
    float* wq = &swq[wid * QW];

    const float invR = (float)(1.0 / RMAX_D);

    // ---- Binning pass 1: load 4 pts/thread, histogram cells ----
    if (tid < NCELL) scnt[tid] = 0;
    if (tid < NBINS) sacc[tid] = 0.0f;
    __syncthreads();

    float bxr[PPT], byr[PPT];
    int   cidr[PPT];
#pragma unroll
    for (int k = 0; k < PPT; k++) {
        int j = tid + k * NTHR;
        float x = B[3 * j];
        float y = B[3 * j + 1];
        int cx = min(G - 1, (int)(x * (float)G));
        int cy = min(G - 1, (int)(y * (float)G));
        int c  = cy * G + cx;
        bxr[k] = x * invR;
        byr[k] = y * invR;
        cidr[k] = c;
        atomicAdd(&scnt[c], 1);
    }
    __syncthreads();

    // ---- Exclusive scan of 25 cell counts (warp 0) ----
    if (wid == 0) {
        int c = (lane < NCELL) ? scnt[lane] : 0;
#pragma unroll
        for (int off = 1; off < 32; off <<= 1) {
            int n = __shfl_up_sync(0xFFFFFFFFu, c, off);
            if (lane >= off) c += n;
        }
        if (lane < NCELL) scellstart[lane + 1] = c;
        if (lane == 0)    scellstart[0] = 0;
        if (lane < NCELL) scnt[lane] = 0;    // reuse as scatter cursor
    }
    __syncthreads();

    // ---- Binning pass 2: scatter ----
#pragma unroll
    for (int k = 0; k < PPT; k++) {
        int c = cidr[k];
        int slot = scellstart[c] + atomicAdd(&scnt[c], 1);
        sbp[slot] = make_float2(bxr[k], byr[k]);
        sbj[slot] = (unsigned short)(tid + k * NTHR);
    }

    // ---- This warp's i coords ----
    const float ax = A[3 * i];
    const float ay = A[3 * i + 1];
    const float axs = ax * invR;
    const float ays = ay * invR;

    const float TWO_PI = 6.2831853071795864769f;
    const float ex0 = ax,  ex1 = 1.0f - ax;
    const float ex2v = ay, ex3 = 1.0f - ay;

    // ---- Weights: ONLY sub==0 warp per i, into smem table ----
    if (sub == 0) {
        const float mEdge = fminf(fminf(ex0, ex1), fminf(ex2v, ex3));
        const float rsMax = (float)(5.0 * RMAX_D);
        float w1 = 1.0f, w2 = 1.0f;
        if (mEdge < rsMax) {            // warp-uniform: i near a border
            float aval = 0.0f;
            if (lane < 8) {
                int e     = lane >> 1;
                int which = lane & 1;
                float exk = (e == 0) ? ax : (e == 1) ? (1.0f - ax)
                          : (e == 2) ? ay : (1.0f - ay);
                float eyk = (e < 2) ? ay : ax;
                float yy  = which ? (1.0f - eyk) : eyk;
                aval = atan2_q1(yy, exk);
            }
            const float a10 = __shfl_sync(0xFFFFFFFFu, aval, 0);
            const float a20 = __shfl_sync(0xFFFFFFFFu, aval, 1);
            const float a11 = __shfl_sync(0xFFFFFFFFu, aval, 2);
            const float a21 = __shfl_sync(0xFFFFFFFFu, aval, 3);
            const float a12 = __shfl_sync(0xFFFFFFFFu, aval, 4);
            const float a22 = __shfl_sync(0xFFFFFFFFu, aval, 5);
            const float a13 = __shfl_sync(0xFFFFFFFFu, aval, 6);
            const float a23 = __shfl_sync(0xFFFFFFFFu, aval, 7);

            const float rs1 = (float)((lane +  1) * (5.0 / 50.0) * RMAX_D);
            const float rs2 = (float)((lane + 33) * (5.0 / 50.0) * RMAX_D);
            {
                float ir = rcp_fast(rs1);
                float al0 = acos_poly(fminf(ex0  * ir, 1.0f));
                float al1 = acos_poly(fminf(ex1  * ir, 1.0f));
                float al2 = acos_poly(fminf(ex2v * ir, 1.0f));
                float al3 = acos_poly(fminf(ex3  * ir, 1.0f));
                float full = TWO_PI
                    - (fminf(al0, a10) + fminf(al0, a20))
                    - (fminf(al1, a11) + fminf(al1, a21))
                    - (fminf(al2, a12) + fminf(al2, a22))
                    - (fminf(al3, a13) + fminf(al3, a23));
                float per = fminf(fmaxf(full * (1.0f / TWO_PI), 0.0f), 1.0f);
                w1 = fminf(rcp_fast(fmaxf(per, 1e-9f)), 4.0f);
            }
            {
                float ir = rcp_fast(rs2);
                float al0 = acos_poly(fminf(ex0  * ir, 1.0f));
                float al1 = acos_poly(fminf(ex1  * ir, 1.0f));
                float al2 = acos_poly(fminf(ex2v * ir, 1.0f));
                float al3 = acos_poly(fminf(ex3  * ir, 1.0f));
                float full = TWO_PI
                    - (fminf(al0, a10) + fminf(al0, a20))
                    - (fminf(al1, a11) + fminf(al1, a21))
                    - (fminf(al2, a12) + fminf(al2, a22))
                    - (fminf(al3, a13) + fminf(al3, a23));
                float per = fminf(fmaxf(full * (1.0f / TWO_PI), 0.0f), 1.0f);
                w2 = fminf(rcp_fast(fmaxf(per, 1e-9f)), 4.0f);
            }
        }
        if (lane >= NBINS - 32) w2 = 0.0f;   // dead bins contribute 0
        sw12[iloc * 32 + lane] = make_float2(w1, w2);
    }

    const int   same = *scp;
    const float cut2 = (5.0f + ZC) * (5.0f + ZC);   // u-units

    __syncthreads();   // sbp/sbj/scellstart/sw12 ready

    // ---- Phase A: this warp scans ONE neighbor cell-row of its i ----
    int cix = min(G - 1, (int)(ax * (float)G));
    int ciy = min(G - 1, (int)(ay * (float)G));
    int cxlo = max(cix - 1, 0), cxhi = min(cix + 1, G - 1);
    int cylo = max(ciy - 1, 0), cyhi = min(ciy + 1, G - 1);
    int r    = cylo + sub;                   // this warp's row

    int cnt = 0;
    if (r <= cyhi) {
        int lo = scellstart[r * G + cxlo];
        int hi = scellstart[r * G + cxhi + 1];
        const unsigned lt_mask = (1u << lane) - 1u;
        for (int base = lo; base < hi; base += 32) {
            int jl = base + lane;
            int jc = min(jl, NPTS - 1);
            float2 p = sbp[jc];
            float dx = axs - p.x;
            float dy = ays - p.y;
            float d2 = fmaf(dx, dx, dy * dy);
            bool pred = (jl < hi) && (d2 < cut2)
                        && !(same && i == (int)sbj[jc]);
            unsigned mask = __ballot_sync(0xFFFFFFFFu, pred);
            if (pred) {
                int slot = cnt + __popc(mask & lt_mask);
                if (slot < QW) wq[slot] = sqrtf(d2);   // u = d/RMAX
            }
            cnt += __popc(mask);
        }
        if (cnt > QW) cnt = QW;
    }
    if (lane == 0) scnt_w[wid] = cnt;
    __syncthreads();   // all queues + counts visible block-wide

    // ---- Phase B: ALL warps drain ALL queues (balanced, strided) ----
    const float L2E = 1.4426950408889634f;
    const float c2  = -16.0f * L2E;
    const float zb1 = 0.1f * (float)(lane + 1);
    const float zb2 = zb1 + 3.2f;
    const float c1a = 32.0f * zb1 * L2E;
    const float c0a = -16.0f * zb1 * zb1 * L2E;
    const float c1b = 32.0f * zb2 * L2E;
    const float c0b = -16.0f * zb2 * zb2 * L2E;

    float acc1 = 0.0f, acc2 = 0.0f;
#pragma unroll
    for (int q = 0; q < NWARP; q++) {
        const int iq = q / 3;                       // compile-time per q
        const float2 ww = sw12[iq * 32 + lane];     // uniform for queue
        const float* qq = &swq[q * QW];
        const int n = scnt_w[q];
        int e = wid;
        for (; e + NWARP < n; e += 2 * NWARP) {
            float uA  = qq[e];
            float uB  = qq[e + NWARP];
            float uA2 = uA * uA;
            float uB2 = uB * uB;
            float gA1 = ex2_fast(fmaf(c2, uA2, fmaf(c1a, uA, c0a)));
            float gB1 = ex2_fast(fmaf(c2, uB2, fmaf(c1a, uB, c0a)));
            float gA2 = ex2_fast(fmaf(c2, uA2, fmaf(c1b, uA, c0b)));
            float gB2 = ex2_fast(fmaf(c2, uB2, fmaf(c1b, uB, c0b)));
            acc1 = fmaf(gA1, ww.x, acc1);
            acc1 = fmaf(gB1, ww.x, acc1);
            acc2 = fmaf(gA2, ww.y, acc2);
            acc2 = fmaf(gB2, ww.y, acc2);
        }
        if (e < n) {
            float u  = qq[e];
            float u2 = u * u;
            acc1 = fmaf(ex2_fast(fmaf(c2, u2, fmaf(c1a, u, c0a))), ww.x, acc1);
            acc2 = fmaf(ex2_fast(fmaf(c2, u2, fmaf(c1b, u, c0b))), ww.y, acc2);
        }
    }

    // ---- Block reduction -> global ----
    atomicAdd(&sacc[lane], acc1);
    if (lane < NBINS - 32) atomicAdd(&sacc[lane + 32], acc2);
    __syncthreads();
    if (tid < NBINS) atomicAdd(&g_acc[tid], sacc[tid]);

    // ---- Last block finalizes ----
    __threadfence();
    if (tid == 0) {
        int v = atomicAdd(&g_done, 1);
        is_last = (v == NBLK - 1);
    }
    __syncthreads();
    if (is_last) {
        if (tid < NBINS) {
            int b = tid;
            double rs_d  = (b + 1) * (5.0 / 50.0) * RMAX_D;
            double inner = fmax(0.0, rs_d - 0.5 * RMAX_D);
            double outer = rs_d + 0.5 * RMAX_D;
            float  area  = (float)(M_PI * (outer * outer - inner * inner));
            const float GF = (float)(1.0 / (sqrt(M_PI) * 0.25));

            float s   = g_acc[b] * GF;
            float pcf = s / 1536.0f / (area * 1536.0f);

            out[2 * b]     = (float)rs_d / (float)RMAX_D;
            out[2 * b + 1] = pcf;

            g_acc[b] = 0.0f;          // reset for next graph replay
        }
        if (tid == 0) g_done = 0;
    }
}

// ---------------------------------------------------------------------------
extern "C" void kernel_launch(void* const* d_in, const int* in_sizes, int n_in,
                              void* d_out, int out_size)
{
    const float* A  = (const float*)d_in[0];   // disks_a [1536,3]
    const float* B  = (const float*)d_in[1];   // disks_b [1536,3]
    const int*   sc = (const int*)d_in[2];     // same_category scalar
    float* out = (float*)d_out;

    pcf_kernel<<<NBLK, NTHR>>>(A, B, sc, out);
}